// round 2
// baseline (speedup 1.0000x reference)
#include <cuda_runtime.h>
#include <math.h>

// ---------------------------------------------------------------------------
// Scratch: masked weight matrices (timestep-invariant). Static __device__
// arrays (no allocation). Max problem size 1024x1024 per matrix.
// ---------------------------------------------------------------------------
__device__ float g_Wc[1024 * 1024];   // kernel * u_current            [D, U]
__device__ float g_Wp[1024 * 1024];   // recurrent_kernel * u_previous [U, U]

// ---------------------------------------------------------------------------
// Build masked weights.  One block per unit (column u).
//   e_d   = exp(-(idx_d - mu_u)^2 / (2 * clip(sigma_u)^2)),  idx_d = d/(n_in-1)
//   row_u normalized by its l2 norm, scaled by sqrt(input_dim)
//   Wm[d, u] = W[d, u] * e_d * scale / norm_u
// ---------------------------------------------------------------------------
__global__ void build_mask_kernel(const float* __restrict__ W,
                                  const float* __restrict__ mu,
                                  const float* __restrict__ sigma,
                                  float* __restrict__ Wm,
                                  int n_in, int units, float scale) {
    int u = blockIdx.x;
    float m = mu[u];
    float s = sigma[u];
    s = fminf(fmaxf(s, 0.01f), 1.0f);
    float inv2s2 = 1.0f / (2.0f * s * s);
    float inv_nm1 = 1.0f / (float)(n_in - 1);

    // sum of squares of the mask row
    float ss = 0.0f;
    for (int d = threadIdx.x; d < n_in; d += blockDim.x) {
        float diff = (float)d * inv_nm1 - m;
        float e = expf(-diff * diff * inv2s2);
        ss += e * e;
    }
    __shared__ float red[32];
    #pragma unroll
    for (int o = 16; o > 0; o >>= 1) ss += __shfl_down_sync(0xffffffffu, ss, o);
    if ((threadIdx.x & 31) == 0) red[threadIdx.x >> 5] = ss;
    __syncthreads();
    if (threadIdx.x < 32) {
        int nwarp = (blockDim.x + 31) >> 5;
        float v = (threadIdx.x < nwarp) ? red[threadIdx.x] : 0.0f;
        #pragma unroll
        for (int o = 16; o > 0; o >>= 1) v += __shfl_down_sync(0xffffffffu, v, o);
        if (threadIdx.x == 0) red[0] = v;
    }
    __syncthreads();
    float factor = scale * rsqrtf(red[0]);

    for (int d = threadIdx.x; d < n_in; d += blockDim.x) {
        float diff = (float)d * inv_nm1 - m;
        float e = expf(-diff * diff * inv2s2);
        Wm[(size_t)d * units + u] = W[(size_t)d * units + u] * (e * factor);
    }
}

// ---------------------------------------------------------------------------
// Tiled fp32 GEMM with fused epilogue.
//   C[m, n] = f( A[m, :] dot Bm[:, n]  (+ bias[n])  (+ Z[m, n]) )
//   f = tanh if TANH.
// A: row-major with leading dim lda (row stride in floats)
// Bm: row-major [K, N] (ldb == N)
// C/Z: row-major with leading dims ldc/ldz.
// Assumes M % BM == 0, N % BN == 0, K % BK == 0, BK % 4 == 0, BN % 4 == 0.
// Thread block: (BM/4)*(BN/4) threads, each computes a 4x4 micro-tile.
// ---------------------------------------------------------------------------
template <int BM, int BN, int BK, bool HAS_BIAS, bool HAS_Z, bool TANH>
__global__ void gemm_fused(const float* __restrict__ A, int lda,
                           const float* __restrict__ Bm,
                           const float* __restrict__ bias,
                           const float* __restrict__ Z, int ldz,
                           float* __restrict__ C, int ldc,
                           int N, int K) {
    constexpr int TM = 4, TN = 4;
    constexpr int THREADS = (BM / TM) * (BN / TN);

    __shared__ float As[BK][BM];   // transposed A tile
    __shared__ float Bs[BK][BN];

    const int tid = threadIdx.x;
    const int tx = tid % (BN / TN);
    const int ty = tid / (BN / TN);
    const int m0 = blockIdx.y * BM;
    const int n0 = blockIdx.x * BN;

    // A-tile loader mapping (float4 along K, store transposed)
    constexpr int A_TPR = BK / 4;              // float4 slots per A row
    constexpr int A_RSTRIDE = THREADS / A_TPR; // rows covered per pass
    const int aRow = tid / A_TPR;
    const int aCol = (tid % A_TPR) * 4;
    // B-tile loader mapping (float4 along N)
    constexpr int B_TPR = BN / 4;
    constexpr int B_RSTRIDE = THREADS / B_TPR;
    const int bRow = tid / B_TPR;
    const int bCol = (tid % B_TPR) * 4;

    float acc[TM][TN];
    #pragma unroll
    for (int i = 0; i < TM; i++)
        #pragma unroll
        for (int j = 0; j < TN; j++) acc[i][j] = 0.0f;

    for (int k0 = 0; k0 < K; k0 += BK) {
        #pragma unroll
        for (int r = aRow; r < BM; r += A_RSTRIDE) {
            float4 v = *(const float4*)&A[(size_t)(m0 + r) * lda + k0 + aCol];
            As[aCol + 0][r] = v.x;
            As[aCol + 1][r] = v.y;
            As[aCol + 2][r] = v.z;
            As[aCol + 3][r] = v.w;
        }
        #pragma unroll
        for (int r = bRow; r < BK; r += B_RSTRIDE) {
            *(float4*)&Bs[r][bCol] =
                *(const float4*)&Bm[(size_t)(k0 + r) * N + n0 + bCol];
        }
        __syncthreads();

        #pragma unroll
        for (int kk = 0; kk < BK; kk++) {
            float a[TM], b[TN];
            *(float4*)a = *(const float4*)&As[kk][ty * TM];
            *(float4*)b = *(const float4*)&Bs[kk][tx * TN];
            #pragma unroll
            for (int i = 0; i < TM; i++)
                #pragma unroll
                for (int j = 0; j < TN; j++) acc[i][j] += a[i] * b[j];
        }
        __syncthreads();
    }

    // Epilogue
    float4 bb = make_float4(0.f, 0.f, 0.f, 0.f);
    if (HAS_BIAS) bb = *(const float4*)&bias[n0 + tx * TN];
    #pragma unroll
    for (int i = 0; i < TM; i++) {
        const int m = m0 + ty * TM + i;
        const int n = n0 + tx * TN;
        float v[TN];
        #pragma unroll
        for (int j = 0; j < TN; j++) v[j] = acc[i][j];
        if (HAS_BIAS) {
            v[0] += bb.x; v[1] += bb.y; v[2] += bb.z; v[3] += bb.w;
        }
        if (HAS_Z) {
            float4 z = *(const float4*)&Z[(size_t)m * ldz + n];
            v[0] += z.x; v[1] += z.y; v[2] += z.z; v[3] += z.w;
        }
        if (TANH) {
            #pragma unroll
            for (int j = 0; j < TN; j++) v[j] = tanhf(v[j]);
        }
        float4 o = make_float4(v[0], v[1], v[2], v[3]);
        *(float4*)&C[(size_t)m * ldc + n] = o;
    }
}

// ---------------------------------------------------------------------------
// Launch.
// Inputs (metadata order):
//  0 inputs [B,T,D]  1 h0 [B,U]  2 kernel [D,U]  3 recurrent_kernel [U,U]
//  4 bias [U]        5 mu_current [U]  6 sigma_current [U]
//  7 mu_prev [U]     8 sigma_prev [U]
// Output: [B,T,U] float32.
// ---------------------------------------------------------------------------
extern "C" void kernel_launch(void* const* d_in, const int* in_sizes, int n_in,
                              void* d_out, int out_size) {
    const float* X    = (const float*)d_in[0];
    const float* h0   = (const float*)d_in[1];
    const float* Wk   = (const float*)d_in[2];
    const float* Wr   = (const float*)d_in[3];
    const float* bias = (const float*)d_in[4];
    const float* muc  = (const float*)d_in[5];
    const float* sic  = (const float*)d_in[6];
    const float* mup  = (const float*)d_in[7];
    const float* sip  = (const float*)d_in[8];
    float* out = (float*)d_out;

    const int U = in_sizes[4];
    const int D = in_sizes[2] / U;
    const int B = in_sizes[1] / U;
    const int T = in_sizes[0] / (B * D);

    float* Wc;
    float* Wp;
    cudaGetSymbolAddress((void**)&Wc, g_Wc);
    cudaGetSymbolAddress((void**)&Wp, g_Wp);

    const float scale = sqrtf((float)D);  // reference uses sqrt(D) for BOTH masks

    // 1) Masked weights (tiny)
    build_mask_kernel<<<U, 256>>>(Wk, muc, sic, Wc, D, U, scale);
    build_mask_kernel<<<U, 256>>>(Wr, mup, sip, Wp, U, U, scale);

    // 2) Z = X @ Wc + bias  -> written straight into d_out
    {
        constexpr int BM = 64, BN = 64, BK = 16;
        dim3 grid(U / BN, (B * T) / BM);
        dim3 block((BM / 4) * (BN / 4));
        gemm_fused<BM, BN, BK, /*BIAS*/true, /*Z*/false, /*TANH*/false>
            <<<grid, block>>>(X, D, Wc, bias, nullptr, 0, out, U, U, D);
    }

    // 3) Recurrent scan: out[:,t,:] = tanh(Z_t + h_{t-1} @ Wp)
    {
        constexpr int BM = 32, BN = 64, BK = 16;
        dim3 grid(U / BN, B / BM);
        dim3 block((BM / 4) * (BN / 4));
        const int ldo = T * U;  // row stride between batches in d_out
        for (int t = 0; t < T; t++) {
            const float* A   = (t == 0) ? h0 : (out + (size_t)(t - 1) * U);
            const int    lda = (t == 0) ? U  : ldo;
            float* Ct = out + (size_t)t * U;  // also the Z term (in place)
            gemm_fused<BM, BN, BK, /*BIAS*/false, /*Z*/true, /*TANH*/true>
                <<<grid, block>>>(A, lda, Wp, nullptr, Ct, ldo, Ct, ldo, U, U);
        }
    }
}

// round 3
// speedup vs baseline: 1.1697x; 1.1697x over previous
#include <cuda_runtime.h>
#include <math.h>

using u64 = unsigned long long;

// ---------------------------------------------------------------------------
// Packed fp32x2 helpers (sm_103a FFMA2 path — only reachable via PTX).
// Pairs are along the M dimension: a pair holds rows (m, m+1) of one column.
// ---------------------------------------------------------------------------
__device__ __forceinline__ u64 pack_dup(float v) {
    u64 r; asm("mov.b64 %0, {%1, %1};" : "=l"(r) : "f"(v)); return r;
}
__device__ __forceinline__ void unpack2(u64 p, float& lo, float& hi) {
    asm("mov.b64 {%0, %1}, %2;" : "=f"(lo), "=f"(hi) : "l"(p));
}
__device__ __forceinline__ u64 ffma2(u64 a, u64 b, u64 c) {
    u64 d; asm("fma.rn.f32x2 %0, %1, %2, %3;" : "=l"(d) : "l"(a), "l"(b), "l"(c));
    return d;
}

// ---------------------------------------------------------------------------
// Scratch: masked weight matrices (timestep-invariant). Static __device__
// arrays (no allocation).
// ---------------------------------------------------------------------------
__device__ float g_Wc[1024 * 1024];   // kernel * u_current            [D, U]
__device__ float g_Wp[1024 * 1024];   // recurrent_kernel * u_previous [U, U]

// ---------------------------------------------------------------------------
// Build masked weights.  One block per unit (column u).
// ---------------------------------------------------------------------------
__global__ void build_mask_kernel(const float* __restrict__ W,
                                  const float* __restrict__ mu,
                                  const float* __restrict__ sigma,
                                  float* __restrict__ Wm,
                                  int n_in, int units, float scale) {
    int u = blockIdx.x;
    float m = mu[u];
    float s = sigma[u];
    s = fminf(fmaxf(s, 0.01f), 1.0f);
    float inv2s2 = 1.0f / (2.0f * s * s);
    float inv_nm1 = 1.0f / (float)(n_in - 1);

    float ss = 0.0f;
    for (int d = threadIdx.x; d < n_in; d += blockDim.x) {
        float diff = (float)d * inv_nm1 - m;
        float e = expf(-diff * diff * inv2s2);
        ss += e * e;
    }
    __shared__ float red[32];
    #pragma unroll
    for (int o = 16; o > 0; o >>= 1) ss += __shfl_down_sync(0xffffffffu, ss, o);
    if ((threadIdx.x & 31) == 0) red[threadIdx.x >> 5] = ss;
    __syncthreads();
    if (threadIdx.x < 32) {
        int nwarp = (blockDim.x + 31) >> 5;
        float v = (threadIdx.x < nwarp) ? red[threadIdx.x] : 0.0f;
        #pragma unroll
        for (int o = 16; o > 0; o >>= 1) v += __shfl_down_sync(0xffffffffu, v, o);
        if (threadIdx.x == 0) red[0] = v;
    }
    __syncthreads();
    float factor = scale * rsqrtf(red[0]);

    for (int d = threadIdx.x; d < n_in; d += blockDim.x) {
        float diff = (float)d * inv_nm1 - m;
        float e = expf(-diff * diff * inv2s2);
        Wm[(size_t)d * units + u] = W[(size_t)d * units + u] * (e * factor);
    }
}

// ---------------------------------------------------------------------------
// Big GEMM: C[m,n] = A[m,:] . B[:,n] + bias[n]
// Tiles: BM=128, BN=128, BK=16, 256 threads, micro-tile 8x8 (4 M-pairs x 8 N).
// FFMA2 throughput-bound design: per kk per thread 4 LDS + 8 mov + 32 FFMA2.
// ---------------------------------------------------------------------------
__global__ void __launch_bounds__(256) gemm_big_kernel(
    const float* __restrict__ A, int lda,
    const float* __restrict__ Bm,
    const float* __restrict__ bias,
    float* __restrict__ C, int ldc,
    int N, int K)
{
    __shared__ __align__(16) float As[16][128];   // transposed A tile [k][m]
    __shared__ __align__(16) float Bs[16][128];   // B tile [k][n]

    const int tid = threadIdx.x;
    const int tx = tid & 15;          // n group
    const int ty = tid >> 4;          // m group (0..15)
    const int m0 = blockIdx.y * 128;
    const int n0 = blockIdx.x * 128;
    const int mt = ty * 8;
    const int nt = tx * 8;

    const int aRow = tid >> 2;            // 0..63 (+64)
    const int aCol = (tid & 3) * 4;
    const int bRow = tid >> 5;            // 0..7 (+8)
    const int bCol = (tid & 31) * 4;

    u64 acc[4][8];
    #pragma unroll
    for (int i = 0; i < 4; i++)
        #pragma unroll
        for (int j = 0; j < 8; j++) acc[i][j] = 0ull;   // (0.f, 0.f)

    for (int k0 = 0; k0 < K; k0 += 16) {
        #pragma unroll
        for (int r = 0; r < 2; r++) {
            int mr = aRow + r * 64;
            float4 v = *(const float4*)&A[(size_t)(m0 + mr) * lda + k0 + aCol];
            As[aCol + 0][mr] = v.x;
            As[aCol + 1][mr] = v.y;
            As[aCol + 2][mr] = v.z;
            As[aCol + 3][mr] = v.w;
        }
        #pragma unroll
        for (int r = 0; r < 2; r++) {
            int kr = bRow + r * 8;
            *(float4*)&Bs[kr][bCol] =
                *(const float4*)&Bm[(size_t)(k0 + kr) * N + n0 + bCol];
        }
        __syncthreads();

        #pragma unroll
        for (int kk = 0; kk < 16; kk++) {
            ulonglong2 a01 = *(const ulonglong2*)&As[kk][mt];
            ulonglong2 a23 = *(const ulonglong2*)&As[kk][mt + 4];
            float4 b0 = *(const float4*)&Bs[kk][nt];
            float4 b1 = *(const float4*)&Bs[kk][nt + 4];
            u64 ap[4] = {a01.x, a01.y, a23.x, a23.y};
            u64 bd[8] = {pack_dup(b0.x), pack_dup(b0.y), pack_dup(b0.z), pack_dup(b0.w),
                         pack_dup(b1.x), pack_dup(b1.y), pack_dup(b1.z), pack_dup(b1.w)};
            #pragma unroll
            for (int i = 0; i < 4; i++)
                #pragma unroll
                for (int j = 0; j < 8; j++)
                    acc[i][j] = ffma2(ap[i], bd[j], acc[i][j]);
        }
        __syncthreads();
    }

    // Epilogue: + bias, store 8 rows x 8 cols
    float bv[8];
    {
        float4 b0 = *(const float4*)&bias[n0 + nt];
        float4 b1 = *(const float4*)&bias[n0 + nt + 4];
        bv[0] = b0.x; bv[1] = b0.y; bv[2] = b0.z; bv[3] = b0.w;
        bv[4] = b1.x; bv[5] = b1.y; bv[6] = b1.z; bv[7] = b1.w;
    }
    #pragma unroll
    for (int i = 0; i < 4; i++) {
        float lo[8], hi[8];
        #pragma unroll
        for (int j = 0; j < 8; j++) unpack2(acc[i][j], lo[j], hi[j]);
        const int mr = m0 + mt + 2 * i;
        float* c0 = &C[(size_t)mr * ldc + n0 + nt];
        float* c1 = &C[(size_t)(mr + 1) * ldc + n0 + nt];
        *(float4*)&c0[0] = make_float4(lo[0] + bv[0], lo[1] + bv[1], lo[2] + bv[2], lo[3] + bv[3]);
        *(float4*)&c0[4] = make_float4(lo[4] + bv[4], lo[5] + bv[5], lo[6] + bv[6], lo[7] + bv[7]);
        *(float4*)&c1[0] = make_float4(hi[0] + bv[0], hi[1] + bv[1], hi[2] + bv[2], hi[3] + bv[3]);
        *(float4*)&c1[4] = make_float4(hi[4] + bv[4], hi[5] + bv[5], hi[6] + bv[6], hi[7] + bv[7]);
    }
}

// ---------------------------------------------------------------------------
// Recurrent step GEMM: C[m,n] = tanh( Z[m,n] + A[m,:] . B[:,n] ), in place OK.
// Tiles: BM=16, BN=64, BK=16, 128 threads, micro-tile 2x4 (1 M-pair x 4 N).
// Optimized for occupancy/latency (256 CTAs on chip for the serial chain).
// ---------------------------------------------------------------------------
__global__ void __launch_bounds__(128) gemm_step_kernel(
    const float* __restrict__ A, int lda,
    const float* __restrict__ Bm,
    const float* __restrict__ Z, int ldz,
    float* __restrict__ C, int ldc,
    int N, int K)
{
    __shared__ __align__(16) float As[16][16];   // transposed A tile [k][m]
    __shared__ __align__(16) float Bs[16][64];   // B tile [k][n]

    const int tid = threadIdx.x;
    const int tx = tid & 15;          // n group
    const int ty = tid >> 4;          // 0..7 -> m pair
    const int m0 = blockIdx.y * 16;
    const int n0 = blockIdx.x * 64;
    const int mt = ty * 2;
    const int nt = tx * 4;

    const int aRow = tid >> 2;            // valid for tid<64: 0..15
    const int aCol = (tid & 3) * 4;
    const int bRow = tid >> 4;            // 0..7 (+8)
    const int bCol = (tid & 15) * 4;

    u64 acc[4] = {0ull, 0ull, 0ull, 0ull};

    for (int k0 = 0; k0 < K; k0 += 16) {
        if (tid < 64) {
            float4 v = *(const float4*)&A[(size_t)(m0 + aRow) * lda + k0 + aCol];
            As[aCol + 0][aRow] = v.x;
            As[aCol + 1][aRow] = v.y;
            As[aCol + 2][aRow] = v.z;
            As[aCol + 3][aRow] = v.w;
        }
        #pragma unroll
        for (int r = 0; r < 2; r++) {
            int kr = bRow + r * 8;
            *(float4*)&Bs[kr][bCol] =
                *(const float4*)&Bm[(size_t)(k0 + kr) * N + n0 + bCol];
        }
        __syncthreads();

        #pragma unroll
        for (int kk = 0; kk < 16; kk++) {
            u64 ap = *(const u64*)&As[kk][mt];
            float4 b = *(const float4*)&Bs[kk][nt];
            acc[0] = ffma2(ap, pack_dup(b.x), acc[0]);
            acc[1] = ffma2(ap, pack_dup(b.y), acc[1]);
            acc[2] = ffma2(ap, pack_dup(b.z), acc[2]);
            acc[3] = ffma2(ap, pack_dup(b.w), acc[3]);
        }
        __syncthreads();
    }

    float lo[4], hi[4];
    #pragma unroll
    for (int j = 0; j < 4; j++) unpack2(acc[j], lo[j], hi[j]);

    const int mr = m0 + mt;
    float4 z0 = *(const float4*)&Z[(size_t)mr * ldz + n0 + nt];
    float4 z1 = *(const float4*)&Z[(size_t)(mr + 1) * ldz + n0 + nt];
    float4 o0 = make_float4(tanhf(lo[0] + z0.x), tanhf(lo[1] + z0.y),
                            tanhf(lo[2] + z0.z), tanhf(lo[3] + z0.w));
    float4 o1 = make_float4(tanhf(hi[0] + z1.x), tanhf(hi[1] + z1.y),
                            tanhf(hi[2] + z1.z), tanhf(hi[3] + z1.w));
    *(float4*)&C[(size_t)mr * ldc + n0 + nt] = o0;
    *(float4*)&C[(size_t)(mr + 1) * ldc + n0 + nt] = o1;
}

// ---------------------------------------------------------------------------
// Launch.
// Inputs (metadata order):
//  0 inputs [B,T,D]  1 h0 [B,U]  2 kernel [D,U]  3 recurrent_kernel [U,U]
//  4 bias [U]        5 mu_current [U]  6 sigma_current [U]
//  7 mu_prev [U]     8 sigma_prev [U]
// Output: [B,T,U] float32.
// ---------------------------------------------------------------------------
extern "C" void kernel_launch(void* const* d_in, const int* in_sizes, int n_in,
                              void* d_out, int out_size) {
    const float* X    = (const float*)d_in[0];
    const float* h0   = (const float*)d_in[1];
    const float* Wk   = (const float*)d_in[2];
    const float* Wr   = (const float*)d_in[3];
    const float* bias = (const float*)d_in[4];
    const float* muc  = (const float*)d_in[5];
    const float* sic  = (const float*)d_in[6];
    const float* mup  = (const float*)d_in[7];
    const float* sip  = (const float*)d_in[8];
    float* out = (float*)d_out;

    const int U = in_sizes[4];
    const int D = in_sizes[2] / U;
    const int B = in_sizes[1] / U;
    const int T = in_sizes[0] / (B * D);

    float* Wc;
    float* Wp;
    cudaGetSymbolAddress((void**)&Wc, g_Wc);
    cudaGetSymbolAddress((void**)&Wp, g_Wp);

    const float scale = sqrtf((float)D);  // reference uses sqrt(D) for BOTH masks

    // 1) Masked weights (tiny)
    build_mask_kernel<<<U, 256>>>(Wk, muc, sic, Wc, D, U, scale);
    build_mask_kernel<<<U, 256>>>(Wr, mup, sip, Wp, U, U, scale);

    // 2) Z = X @ Wc + bias  -> written straight into d_out
    {
        dim3 grid(U / 128, (B * T) / 128);
        gemm_big_kernel<<<grid, 256>>>(X, D, Wc, bias, out, U, U, D);
    }

    // 3) Recurrent scan: out[:,t,:] = tanh(Z_t + h_{t-1} @ Wp)
    {
        dim3 grid(U / 64, B / 16);
        const int ldo = T * U;  // row stride between batches in d_out
        for (int t = 0; t < T; t++) {
            const float* A   = (t == 0) ? h0 : (out + (size_t)(t - 1) * U);
            const int    lda = (t == 0) ? U  : ldo;
            float* Ct = out + (size_t)t * U;  // Z term (in place)
            gemm_step_kernel<<<grid, 128>>>(A, lda, Wp, Ct, ldo, Ct, ldo, U, U);
        }
    }
}